// round 9
// baseline (speedup 1.0000x reference)
#include <cuda_runtime.h>
#include <cuda_bf16.h>
#include <cstdint>

#define BATCH 2048
#define TLEN  200
#define HD    128
#define NA0   64
#define NA1   16
#define NB    16
#define RBLK  (BATCH / NB)   // 128 scan blocks
#define NR    384            // 3*HD gate rows
#define APITCH 136           // bf16 A pitch: 272B rows -> conflict-free ldmatrix

// ---------------- device scratch (no allocs allowed) ----------------
__device__ float g_att[BATCH * TLEN];            // 1.6 MB attention scores
__device__ float g_qp [BATCH * NA0];             // 0.5 MB qpart
__device__ float g_gi [BATCH * TLEN * NR];       // 629 MB  gi = keys@Wih^T + bih
__device__ uint2 g_wfhi[48 * 8 * 32];            // Wih hi fragments (98KB)
__device__ uint2 g_wflo[48 * 8 * 32];            // Wih lo fragments (98KB)

// ---------------- helpers ----------------
__device__ __forceinline__ unsigned long long ffma2(unsigned long long a,
                                                    unsigned long long b,
                                                    unsigned long long c) {
    unsigned long long d;
    asm("fma.rn.f32x2 %0, %1, %2, %3;" : "=l"(d) : "l"(a), "l"(b), "l"(c));
    return d;
}
__device__ __forceinline__ float2 unpk(unsigned long long v) {
    float2 f;
    asm("mov.b64 {%0, %1}, %2;" : "=f"(f.x), "=f"(f.y) : "l"(v));
    return f;
}
__device__ __forceinline__ float sigm(float x) {
    return __fdividef(1.0f, 1.0f + __expf(-x));
}
__device__ __forceinline__ float tanh_fast(float x) {
    float y;
    asm("tanh.approx.f32 %0, %1;" : "=f"(y) : "f"(x));
    return y;
}
__device__ __forceinline__ float sigm_t(float x) {
    return fmaf(0.5f, tanh_fast(0.5f * x), 0.5f);
}
__device__ __forceinline__ uint32_t pkbf(float lo, float hi) {
    __nv_bfloat16 a = __float2bfloat16(lo), b = __float2bfloat16(hi);
    uint16_t ua = *reinterpret_cast<uint16_t*>(&a);
    uint16_t ub = *reinterpret_cast<uint16_t*>(&b);
    return (uint32_t)ua | ((uint32_t)ub << 16);
}
__device__ __forceinline__ void mma16816(float& c0, float& c1, float& c2, float& c3,
                                         uint32_t a0, uint32_t a1, uint32_t a2, uint32_t a3,
                                         uint32_t b0, uint32_t b1) {
    asm volatile(
        "mma.sync.aligned.m16n8k16.row.col.f32.bf16.bf16.f32 "
        "{%0,%1,%2,%3}, {%4,%5,%6,%7}, {%8,%9}, {%0,%1,%2,%3};"
        : "+f"(c0), "+f"(c1), "+f"(c2), "+f"(c3)
        : "r"(a0), "r"(a1), "r"(a2), "r"(a3), "r"(b0), "r"(b1));
}
__device__ __forceinline__ void ldmx4(uint32_t& r0, uint32_t& r1, uint32_t& r2, uint32_t& r3,
                                      uint32_t addr) {
    asm volatile("ldmatrix.sync.aligned.m8n8.x4.shared.b16 {%0,%1,%2,%3}, [%4];"
                 : "=r"(r0), "=r"(r1), "=r"(r2), "=r"(r3) : "r"(addr));
}

// ============================================================================
// Kernel W: build Wih bf16 hi/lo fragments in global (once).
// ============================================================================
__global__ void __launch_bounds__(256) wfrag_kernel(const float* __restrict__ Wih)
{
    const int nt   = blockIdx.x;
    const int tid  = threadIdx.x;
    const int kc   = tid >> 5;
    const int lane = tid & 31;
    const int gid  = lane >> 2, tig = lane & 3;

    const int n = nt * 8 + gid;
    const float* wr = Wih + n * HD + kc * 16;
    const float w0 = wr[2 * tig],     w1 = wr[2 * tig + 1];
    const float w2 = wr[2 * tig + 8], w3 = wr[2 * tig + 9];
    const __nv_bfloat16 h0 = __float2bfloat16(w0), h1 = __float2bfloat16(w1);
    const __nv_bfloat16 h2 = __float2bfloat16(w2), h3 = __float2bfloat16(w3);
    const int idx = (nt * 8 + kc) * 32 + lane;
    g_wfhi[idx] = make_uint2(pkbf(w0, w1), pkbf(w2, w3));
    g_wflo[idx] = make_uint2(
        pkbf(w0 - __bfloat162float(h0), w1 - __bfloat162float(h1)),
        pkbf(w2 - __bfloat162float(h2), w3 - __bfloat162float(h3)));
}

// ============================================================================
// Kernel 0: qpart[b][o] = b0[o] + sum_j (W0a[o,j]+W0c[o,j]) * q[b][j]
// ============================================================================
__global__ void __launch_bounds__(256) qpart_kernel(
    const float* __restrict__ query, const float* __restrict__ W0,
    const float* __restrict__ b0)
{
    __shared__ float sWeff[NA0 * 132];
    __shared__ float sqq[NB * HD];

    const int tid = threadIdx.x;
    const int b0i = blockIdx.x * NB;

    for (int idx = tid; idx < NA0 * HD; idx += 256) {
        const int o = idx >> 7, j = idx & 127;
        sWeff[o * 132 + j] = W0[o * (4 * HD) + j] + W0[o * (4 * HD) + 2 * HD + j];
    }
    for (int idx = tid; idx < NB * HD; idx += 256)
        sqq[idx] = query[b0i * HD + idx];
    __syncthreads();

    const int o  = tid & 63;
    const int bg = tid >> 6;
    unsigned long long acc[4];
    #pragma unroll
    for (int i = 0; i < 4; i++) acc[i] = 0ull;

    #pragma unroll 4
    for (int jc = 0; jc < HD / 4; jc++) {
        const ulonglong2 w = *reinterpret_cast<const ulonglong2*>(&sWeff[o * 132 + jc * 4]);
        #pragma unroll
        for (int i = 0; i < 4; i++) {
            const ulonglong2 x =
                *reinterpret_cast<const ulonglong2*>(&sqq[(bg * 4 + i) * HD + jc * 4]);
            acc[i] = ffma2(w.x, x.x, acc[i]);
            acc[i] = ffma2(w.y, x.y, acc[i]);
        }
    }
    const float bo = b0[o];
    #pragma unroll
    for (int i = 0; i < 4; i++) {
        const float2 p = unpk(acc[i]);
        g_qp[(b0i + bg * 4 + i) * NA0 + o] = p.x + p.y + bo;
    }
}

// ============================================================================
// Kernel 1: DIN attention via tensor cores (unchanged from R8 — validated).
// ============================================================================
#define OFFA_BHI 0
#define OFFA_BLO (OFFA_BHI + 8 * 8 * 32 * 8)
#define OFFA_AHI (OFFA_BLO + 8 * 8 * 32 * 8)
#define OFFA_ALO (OFFA_AHI + 64 * APITCH * 2)
#define OFFA_SA0 (OFFA_ALO + 64 * APITCH * 2)
#define OFFA_W1  (OFFA_SA0 + 64 * 68 * 4)
#define OFFA_SQ  (OFFA_W1 + NA1 * 65 * 4)
#define OFFA_QP  (OFFA_SQ + HD * 4)
#define OFFA_WD  (OFFA_QP + NA0 * 4)
#define OFFA_B1  (OFFA_WD + NA1 * 4)
#define ATTN_SMEM (OFFA_B1 + NA1 * 4)

__global__ void __launch_bounds__(256) attn_kernel(
    const float* __restrict__ query, const float* __restrict__ keys,
    const float* __restrict__ W0,
    const float* __restrict__ W1, const float* __restrict__ b1,
    const float* __restrict__ Wd, const float* __restrict__ bd,
    const int* __restrict__ klen)
{
    extern __shared__ char smc[];
    uint2* sBhi = reinterpret_cast<uint2*>(smc + OFFA_BHI);
    uint2* sBlo = reinterpret_cast<uint2*>(smc + OFFA_BLO);
    __nv_bfloat16* sAhi = reinterpret_cast<__nv_bfloat16*>(smc + OFFA_AHI);
    __nv_bfloat16* sAlo = reinterpret_cast<__nv_bfloat16*>(smc + OFFA_ALO);
    float* sa0 = reinterpret_cast<float*>(smc + OFFA_SA0);
    float* sW1 = reinterpret_cast<float*>(smc + OFFA_W1);
    float* sq  = reinterpret_cast<float*>(smc + OFFA_SQ);
    float* sqp = reinterpret_cast<float*>(smc + OFFA_QP);
    float* sWd = reinterpret_cast<float*>(smc + OFFA_WD);
    float* sb1 = reinterpret_cast<float*>(smc + OFFA_B1);

    const int b    = blockIdx.x;
    const int tid  = threadIdx.x;
    const int lenb = klen[b];
    const int lane = tid & 31, warp = tid >> 5;
    const int gid  = lane >> 2, tig = lane & 3;

    if (tid < HD) sq[tid] = query[b * HD + tid];
    if (tid < NA0) sqp[tid] = g_qp[b * NA0 + tid];
    if (tid < NA1) { sWd[tid] = Wd[tid]; sb1[tid] = b1[tid]; }
    for (int i = tid; i < NA1 * NA0; i += 256) {
        const int p = i >> 6, o = i & 63;
        sW1[p * 65 + o] = W1[i];
    }
    const float bd0 = bd[0];
    __syncthreads();

    {
        const int kc = warp;
        #pragma unroll
        for (int nt = 0; nt < 8; nt++) {
            const int n = nt * 8 + gid;
            const float* wr = W0 + n * (4 * HD);
            const int j0 = kc * 16 + 2 * tig;
            const int j2 = j0 + 8;
            const float w0 = wr[HD + j0]     - wr[2 * HD + j0]     + wr[3 * HD + j0]     * sq[j0];
            const float w1 = wr[HD + j0 + 1] - wr[2 * HD + j0 + 1] + wr[3 * HD + j0 + 1] * sq[j0 + 1];
            const float w2 = wr[HD + j2]     - wr[2 * HD + j2]     + wr[3 * HD + j2]     * sq[j2];
            const float w3 = wr[HD + j2 + 1] - wr[2 * HD + j2 + 1] + wr[3 * HD + j2 + 1] * sq[j2 + 1];
            const __nv_bfloat16 h0 = __float2bfloat16(w0), h1 = __float2bfloat16(w1);
            const __nv_bfloat16 h2 = __float2bfloat16(w2), h3 = __float2bfloat16(w3);
            const int idx = (kc * 8 + nt) * 32 + lane;
            sBhi[idx] = make_uint2(pkbf(w0, w1), pkbf(w2, w3));
            sBlo[idx] = make_uint2(
                pkbf(w0 - __bfloat162float(h0), w1 - __bfloat162float(h1)),
                pkbf(w2 - __bfloat162float(h2), w3 - __bfloat162float(h3)));
        }
    }
    __syncthreads();

    const int mt = warp & 3;
    const int nh = warp >> 2;
    const int lm_m = lane >> 3, lm_r = lane & 7;
    const int lm_row = mt * 16 + ((lm_m & 1) ? 8 : 0) + lm_r;
    const int lm_col = (lm_m >> 1) * 8;
    const uint32_t aoff = (uint32_t)((lm_row * APITCH + lm_col) * 2);
    const uint32_t ahi_base = (uint32_t)__cvta_generic_to_shared(sAhi) + aoff;
    const uint32_t alo_base = (uint32_t)__cvta_generic_to_shared(sAlo) + aoff;

    for (int t0c = 0; t0c < TLEN; t0c += 64) {
        if (t0c >= lenb) {
            for (int i = tid; i < 64; i += 256) {
                const int tg = t0c + i;
                if (tg < TLEN) g_att[b * TLEN + tg] = 0.0f;
            }
            continue;
        }
        for (int idx = tid; idx < 64 * HD; idx += 256) {
            const int tt = idx >> 7, j = idx & 127;
            const int tg = t0c + tt;
            const float v = (tg < TLEN) ? keys[(b * TLEN + tg) * HD + j] : 0.0f;
            const __nv_bfloat16 h = __float2bfloat16(v);
            sAhi[tt * APITCH + j] = h;
            sAlo[tt * APITCH + j] = __float2bfloat16(v - __bfloat162float(h));
        }
        __syncthreads();

        float c[4][4];
        #pragma unroll
        for (int nt = 0; nt < 4; nt++) {
            const int col = (nh * 4 + nt) * 8 + 2 * tig;
            c[nt][0] = sqp[col]; c[nt][1] = sqp[col + 1];
            c[nt][2] = sqp[col]; c[nt][3] = sqp[col + 1];
        }
        #pragma unroll
        for (int kc = 0; kc < 8; kc++) {
            uint32_t ah0, ah1, ah2, ah3, al0, al1, al2, al3;
            ldmx4(ah0, ah1, ah2, ah3, ahi_base + kc * 32);
            ldmx4(al0, al1, al2, al3, alo_base + kc * 32);
            #pragma unroll
            for (int nt = 0; nt < 4; nt++) {
                const int idx = (kc * 8 + nh * 4 + nt) * 32 + lane;
                const uint2 bh = sBhi[idx];
                const uint2 bl = sBlo[idx];
                mma16816(c[nt][0], c[nt][1], c[nt][2], c[nt][3],
                         ah0, ah1, ah2, ah3, bh.x, bh.y);
                mma16816(c[nt][0], c[nt][1], c[nt][2], c[nt][3],
                         al0, al1, al2, al3, bh.x, bh.y);
                mma16816(c[nt][0], c[nt][1], c[nt][2], c[nt][3],
                         ah0, ah1, ah2, ah3, bl.x, bl.y);
            }
        }
        const int row0 = mt * 16 + gid;
        #pragma unroll
        for (int nt = 0; nt < 4; nt++) {
            const int col = (nh * 4 + nt) * 8 + 2 * tig;
            sa0[row0 * 68 + col]           = sigm(c[nt][0]);
            sa0[row0 * 68 + col + 1]       = sigm(c[nt][1]);
            sa0[(row0 + 8) * 68 + col]     = sigm(c[nt][2]);
            sa0[(row0 + 8) * 68 + col + 1] = sigm(c[nt][3]);
        }
        __syncthreads();

        {
            const int row = tid >> 2, sub = tid & 3;
            float s0 = sb1[sub * 4], s1 = sb1[sub * 4 + 1];
            float s2 = sb1[sub * 4 + 2], s3 = sb1[sub * 4 + 3];
            const float* w1r = &sW1[(sub * 4) * 65];
            #pragma unroll 8
            for (int o = 0; o < NA0; o++) {
                const float a = sa0[row * 68 + o];
                s0 = fmaf(w1r[o], a, s0);
                s1 = fmaf(w1r[65 + o], a, s1);
                s2 = fmaf(w1r[130 + o], a, s2);
                s3 = fmaf(w1r[195 + o], a, s3);
            }
            float part = sWd[sub * 4] * sigm(s0) + sWd[sub * 4 + 1] * sigm(s1)
                       + sWd[sub * 4 + 2] * sigm(s2) + sWd[sub * 4 + 3] * sigm(s3);
            part += __shfl_xor_sync(0xffffffffu, part, 1);
            part += __shfl_xor_sync(0xffffffffu, part, 2);
            if (sub == 0) {
                const int tg = t0c + row;
                if (tg < TLEN)
                    g_att[b * TLEN + tg] = (tg < lenb) ? part + bd0 : 0.0f;
            }
        }
        __syncthreads();
    }
}

// ============================================================================
// Kernel 2: gi GEMM via tensor cores (unchanged from R7 — validated).
// ============================================================================
__global__ void __launch_bounds__(256) gi_kernel(
    const float* __restrict__ keys, const float* __restrict__ bih,
    const int* __restrict__ klen)
{
    __shared__ __nv_bfloat16 sAhi[64 * APITCH];
    __shared__ __nv_bfloat16 sAlo[64 * APITCH];

    const int b    = blockIdx.z;
    const int t0   = blockIdx.x * 64;
    const int r0   = blockIdx.y * 128;
    const int lenb = klen[b];
    if (t0 >= lenb) return;

    const int tid = threadIdx.x;

    for (int idx = tid; idx < 64 * HD; idx += 256) {
        const int tt = idx >> 7, j = idx & 127;
        const int tg = t0 + tt;
        const float v = (tg < TLEN) ? keys[(b * TLEN + tg) * HD + j] : 0.0f;
        const __nv_bfloat16 h = __float2bfloat16(v);
        sAhi[tt * APITCH + j] = h;
        sAlo[tt * APITCH + j] = __float2bfloat16(v - __bfloat162float(h));
    }
    __syncthreads();

    const int lane = tid & 31, warp = tid >> 5;
    const int gid  = lane >> 2, tig = lane & 3;
    const int mt   = warp & 3;
    const int nh   = warp >> 2;

    const int lm_m = lane >> 3, lm_r = lane & 7;
    const int lm_row = mt * 16 + ((lm_m & 1) ? 8 : 0) + lm_r;
    const int lm_col = (lm_m >> 1) * 8;
    const uint32_t aoff = (uint32_t)((lm_row * APITCH + lm_col) * 2);
    const uint32_t ahi_base = (uint32_t)__cvta_generic_to_shared(sAhi) + aoff;
    const uint32_t alo_base = (uint32_t)__cvta_generic_to_shared(sAlo) + aoff;

    float c[8][4];
    #pragma unroll
    for (int nt = 0; nt < 8; nt++) {
        const int col = r0 + (nh * 8 + nt) * 8 + 2 * tig;
        const float bv0 = bih[col], bv1 = bih[col + 1];
        c[nt][0] = bv0; c[nt][1] = bv1; c[nt][2] = bv0; c[nt][3] = bv1;
    }

    const int ntg0 = (r0 >> 3) + nh * 8;

    #pragma unroll
    for (int kc = 0; kc < 8; kc++) {
        uint32_t ah0, ah1, ah2, ah3, al0, al1, al2, al3;
        ldmx4(ah0, ah1, ah2, ah3, ahi_base + kc * 32);
        ldmx4(al0, al1, al2, al3, alo_base + kc * 32);
        #pragma unroll
        for (int nt = 0; nt < 8; nt++) {
            const int idx = ((ntg0 + nt) * 8 + kc) * 32 + lane;
            const uint2 bh = g_wfhi[idx];
            const uint2 bl = g_wflo[idx];
            mma16816(c[nt][0], c[nt][1], c[nt][2], c[nt][3],
                     ah0, ah1, ah2, ah3, bh.x, bh.y);
            mma16816(c[nt][0], c[nt][1], c[nt][2], c[nt][3],
                     al0, al1, al2, al3, bh.x, bh.y);
            mma16816(c[nt][0], c[nt][1], c[nt][2], c[nt][3],
                     ah0, ah1, ah2, ah3, bl.x, bl.y);
        }
    }

    const int row0 = t0 + mt * 16 + gid;
    const int row1 = row0 + 8;
    #pragma unroll
    for (int nt = 0; nt < 8; nt++) {
        const int col = r0 + (nh * 8 + nt) * 8 + 2 * tig;
        if (row0 < TLEN)
            *reinterpret_cast<float2*>(&g_gi[(b * TLEN + row0) * NR + col]) =
                make_float2(c[nt][0], c[nt][1]);
        if (row1 < TLEN)
            *reinterpret_cast<float2*>(&g_gi[(b * TLEN + row1) * NR + col]) =
                make_float2(c[nt][2], c[nt][3]);
    }
}

// ============================================================================
// Kernel 3: AUGRU scan — in-register gate update.
// Warp w owns cols [w*8, w*8+8) across ALL 3 gates (n-tiles at g*128+w*8).
// After the MMA the lane holds r/z/n pre-activations for its own 4 (row,col)
// elements -> gate math in registers, h stored bf16 hi/lo to A arrays.
// ONE sync per step.  3 mma terms use separate accumulators (chain depth 8).
// ============================================================================
#define OFF_BHI  0
#define OFF_BLO  (16 * 8 * 3 * 32 * 8)                // 98304
#define OFF_AHI  (OFF_BLO + 16 * 8 * 3 * 32 * 8)      // 196608
#define OFF_ALO  (OFF_AHI + NB * APITCH * 2)          // 200960
#define REC_SMEM (OFF_ALO + NB * APITCH * 2)          // 205312

__global__ void __launch_bounds__(512, 1) rec_kernel(
    const float* __restrict__ Whh, const float* __restrict__ bhh,
    const int* __restrict__ klen, float* __restrict__ out)
{
    extern __shared__ char smc[];
    uint2* sBhi = reinterpret_cast<uint2*>(smc + OFF_BHI);
    uint2* sBlo = reinterpret_cast<uint2*>(smc + OFF_BLO);
    __nv_bfloat16* sAhi = reinterpret_cast<__nv_bfloat16*>(smc + OFF_AHI);
    __nv_bfloat16* sAlo = reinterpret_cast<__nv_bfloat16*>(smc + OFF_ALO);
    __shared__ int smax;

    const int tid  = threadIdx.x;
    const int lane = tid & 31, warp = tid >> 5;
    const int gid  = lane >> 2, tig = lane & 3;
    const int b0   = blockIdx.x * NB;

    // ---- build B fragments: warp w, kc, gate g; tile n-base = g*128 + w*8 ----
    #pragma unroll
    for (int kc = 0; kc < 8; kc++) {
        #pragma unroll
        for (int g = 0; g < 3; g++) {
            const int n = g * HD + warp * 8 + gid;
            const float* wr = Whh + n * HD + kc * 16;
            const float w0 = wr[2 * tig],     w1 = wr[2 * tig + 1];
            const float w2 = wr[2 * tig + 8], w3 = wr[2 * tig + 9];
            const __nv_bfloat16 h0 = __float2bfloat16(w0), h1 = __float2bfloat16(w1);
            const __nv_bfloat16 h2 = __float2bfloat16(w2), h3 = __float2bfloat16(w3);
            const int idx = ((warp * 8 + kc) * 3 + g) * 32 + lane;
            sBhi[idx] = make_uint2(pkbf(w0, w1), pkbf(w2, w3));
            sBlo[idx] = make_uint2(
                pkbf(w0 - __bfloat162float(h0), w1 - __bfloat162float(h1)),
                pkbf(w2 - __bfloat162float(h2), w3 - __bfloat162float(h3)));
        }
    }
    for (int i = tid; i < NB * APITCH; i += 512) {
        sAhi[i] = __float2bfloat16(0.0f);
        sAlo[i] = __float2bfloat16(0.0f);
    }
    __syncthreads();
    if (tid == 0) {
        int m = 0;
        #pragma unroll
        for (int b = 0; b < NB; b++) m = max(m, klen[b0 + b]);
        smax = m;
    }
    __syncthreads();
    const int tmax = smax;

    const int col  = warp * 8 + 2 * tig;           // this lane's column pair base
    const int len0 = klen[b0 + gid];
    const int len1 = klen[b0 + gid + 8];

    const int lm_m = lane >> 3, lm_r = lane & 7;
    const int lm_row = ((lm_m & 1) ? 8 : 0) + lm_r;
    const int lm_col = (lm_m >> 1) * 8;
    const uint32_t aoff = (uint32_t)((lm_row * APITCH + lm_col) * 2);
    const uint32_t ahi_base = (uint32_t)__cvta_generic_to_shared(sAhi) + aoff;
    const uint32_t alo_base = (uint32_t)__cvta_generic_to_shared(sAlo) + aoff;

    float bb0[3], bb1[3];
    #pragma unroll
    for (int g = 0; g < 3; g++) {
        bb0[g] = bhh[g * HD + col];
        bb1[g] = bhh[g * HD + col + 1];
    }

    const float* gbase0 = &g_gi[(size_t)(b0 + gid) * TLEN * NR + col];
    const float* gbase1 = &g_gi[(size_t)(b0 + gid + 8) * TLEN * NR + col];
    const float* abase0 = &g_att[(b0 + gid) * TLEN];
    const float* abase1 = &g_att[(b0 + gid + 8) * TLEN];

    float h00 = 0.0f, h01 = 0.0f, h10 = 0.0f, h11 = 0.0f;

    for (int t = 0; t < tmax; t++) {
        // ---- prefetch gi + att for this lane's elements (hidden under MMA) ----
        const float* g0 = gbase0 + (size_t)t * NR;
        const float* g1 = gbase1 + (size_t)t * NR;
        const float2 pr0 = *reinterpret_cast<const float2*>(g0);
        const float2 pz0 = *reinterpret_cast<const float2*>(g0 + HD);
        const float2 pn0 = *reinterpret_cast<const float2*>(g0 + 2 * HD);
        const float2 pr1 = *reinterpret_cast<const float2*>(g1);
        const float2 pz1 = *reinterpret_cast<const float2*>(g1 + HD);
        const float2 pn1 = *reinterpret_cast<const float2*>(g1 + 2 * HD);
        const float att0 = abase0[t];
        const float att1 = abase1[t];

        // ---- MMA: 3 terms into 3 accumulator sets (chain depth 8 each) ----
        float cA[3][4], cB[3][4], cC[3][4];
        #pragma unroll
        for (int g = 0; g < 3; g++) {
            cA[g][0] = bb0[g]; cA[g][1] = bb1[g]; cA[g][2] = bb0[g]; cA[g][3] = bb1[g];
            cB[g][0] = 0.0f; cB[g][1] = 0.0f; cB[g][2] = 0.0f; cB[g][3] = 0.0f;
            cC[g][0] = 0.0f; cC[g][1] = 0.0f; cC[g][2] = 0.0f; cC[g][3] = 0.0f;
        }
        #pragma unroll
        for (int kc = 0; kc < 8; kc++) {
            uint32_t ah0, ah1, ah2, ah3, al0, al1, al2, al3;
            ldmx4(ah0, ah1, ah2, ah3, ahi_base + kc * 32);
            ldmx4(al0, al1, al2, al3, alo_base + kc * 32);
            #pragma unroll
            for (int g = 0; g < 3; g++) {
                const int idx = ((warp * 8 + kc) * 3 + g) * 32 + lane;
                const uint2 bh = sBhi[idx];
                const uint2 bl = sBlo[idx];
                mma16816(cA[g][0], cA[g][1], cA[g][2], cA[g][3],
                         ah0, ah1, ah2, ah3, bh.x, bh.y);
                mma16816(cB[g][0], cB[g][1], cB[g][2], cB[g][3],
                         al0, al1, al2, al3, bh.x, bh.y);
                mma16816(cC[g][0], cC[g][1], cC[g][2], cC[g][3],
                         ah0, ah1, ah2, ah3, bl.x, bl.y);
            }
        }
        float c[3][4];
        #pragma unroll
        for (int g = 0; g < 3; g++)
            #pragma unroll
            for (int i = 0; i < 4; i++)
                c[g][i] = cA[g][i] + cB[g][i] + cC[g][i];

        // ---- in-register gate update + h store ----
        if (t < len0) {
            const float rr0 = sigm_t(pr0.x + c[0][0]);
            const float zz0 = sigm_t(pz0.x + c[1][0]) * att0;
            const float nn0 = tanh_fast(pn0.x + rr0 * c[2][0]);
            h00 = (1.0f - zz0) * h00 + zz0 * nn0;
            const float rr1 = sigm_t(pr0.y + c[0][1]);
            const float zz1 = sigm_t(pz0.y + c[1][1]) * att0;
            const float nn1 = tanh_fast(pn0.y + rr1 * c[2][1]);
            h01 = (1.0f - zz1) * h01 + zz1 * nn1;
            const __nv_bfloat16 hb0 = __float2bfloat16(h00);
            const __nv_bfloat16 hb1 = __float2bfloat16(h01);
            *reinterpret_cast<uint32_t*>(&sAhi[gid * APITCH + col]) = pkbf(h00, h01);
            *reinterpret_cast<uint32_t*>(&sAlo[gid * APITCH + col]) =
                pkbf(h00 - __bfloat162float(hb0), h01 - __bfloat162float(hb1));
        }
        if (t < len1) {
            const float rr0 = sigm_t(pr1.x + c[0][2]);
            const float zz0 = sigm_t(pz1.x + c[1][2]) * att1;
            const float nn0 = tanh_fast(pn1.x + rr0 * c[2][2]);
            h10 = (1.0f - zz0) * h10 + zz0 * nn0;
            const float rr1 = sigm_t(pr1.y + c[0][3]);
            const float zz1 = sigm_t(pz1.y + c[1][3]) * att1;
            const float nn1 = tanh_fast(pn1.y + rr1 * c[2][3]);
            h11 = (1.0f - zz1) * h11 + zz1 * nn1;
            const __nv_bfloat16 hb0 = __float2bfloat16(h10);
            const __nv_bfloat16 hb1 = __float2bfloat16(h11);
            *reinterpret_cast<uint32_t*>(&sAhi[(gid + 8) * APITCH + col]) = pkbf(h10, h11);
            *reinterpret_cast<uint32_t*>(&sAlo[(gid + 8) * APITCH + col]) =
                pkbf(h10 - __bfloat162float(hb0), h11 - __bfloat162float(hb1));
        }
        __syncthreads();
    }

    if (len0 > 0)
        *reinterpret_cast<float2*>(&out[(b0 + gid) * HD + col]) = make_float2(h00, h01);
    if (len1 > 0)
        *reinterpret_cast<float2*>(&out[(b0 + gid + 8) * HD + col]) = make_float2(h10, h11);
}

// ============================================================================
extern "C" void kernel_launch(void* const* d_in, const int* in_sizes, int n_in,
                              void* d_out, int out_size)
{
    const float* query = (const float*)d_in[0];
    const float* keys  = (const float*)d_in[1];
    const float* W0    = (const float*)d_in[2];
    const float* b0    = (const float*)d_in[3];
    const float* W1    = (const float*)d_in[4];
    const float* b1    = (const float*)d_in[5];
    const float* Wd    = (const float*)d_in[6];
    const float* bd    = (const float*)d_in[7];
    const float* Wih   = (const float*)d_in[8];
    const float* Whh   = (const float*)d_in[9];
    const float* bih   = (const float*)d_in[10];
    const float* bhh   = (const float*)d_in[11];
    const int*   klen  = (const int*)d_in[12];
    float* out = (float*)d_out;

    cudaFuncSetAttribute(attn_kernel, cudaFuncAttributeMaxDynamicSharedMemorySize, ATTN_SMEM);
    cudaFuncSetAttribute(rec_kernel,  cudaFuncAttributeMaxDynamicSharedMemorySize, REC_SMEM);

    wfrag_kernel<<<48, 256>>>(Wih);
    qpart_kernel<<<BATCH / NB, 256>>>(query, W0, b0);
    attn_kernel<<<BATCH, 256, ATTN_SMEM>>>(query, keys, W0, W1, b1, Wd, bd, klen);
    gi_kernel<<<dim3(4, 3, BATCH), 256>>>(keys, bih, klen);
    rec_kernel<<<RBLK, 512, REC_SMEM>>>(Whh, bhh, klen, out);
}